// round 2
// baseline (speedup 1.0000x reference)
#include <cuda_runtime.h>
#include <cuda_bf16.h>
#include <cstdint>

// ---------------- problem constants ----------------
#define NCH      4
#define LL       4608          // L = nH*nW
#define NW       576           // nW
#define TM       128           // M tile (attn rows per CTA)
#define KC       64            // bf16 K elements per pipeline chunk
#define NCHUNKS  72            // 4608 / 64
#define BNROWS   96            // N padded (81 -> 96)
#define WPITCH   5184          // 72*72
#define XCH      373248        // 72*5184 elements per channel
#define NBLK_M   36            // 4608/128

// ---------------- smem layout (bytes) ----------------
// nz:   [0, 512)        128 floats
// A(s): 1024  + s*16384 128 rows x 128B (64 bf16), s in {0,1}
// B(s): 33792 + s*12288  96 rows x 128B (64 bf16), s in {0,1}
#define SM_NZ       0
#define SM_A(s)     (1024  + (s)*16384)
#define SM_B(s)     (33792 + (s)*12288)
#define SMEM_BYTES  58368

// ---------------- scratch: patches bf16, K-major, padded to 96 rows ----------------
__device__ __nv_bfloat16 g_Bmat[(size_t)NCH * BNROWS * LL];

__device__ __forceinline__ uint32_t smem_to_u32(const void* p) {
    uint32_t a;
    asm("{ .reg .u64 t; cvta.to.shared.u64 t, %1; cvt.u32.u64 %0, t; }" : "=r"(a) : "l"(p));
    return a;
}

__device__ __forceinline__ void ldmx4(uint32_t* r, uint32_t addr) {
    asm volatile("ldmatrix.sync.aligned.m8n8.x4.shared.b16 {%0,%1,%2,%3}, [%4];"
                 : "=r"(r[0]), "=r"(r[1]), "=r"(r[2]), "=r"(r[3]) : "r"(addr));
}

__device__ __forceinline__ void mma16816(float* d, const uint32_t* a,
                                         uint32_t b0, uint32_t b1) {
    asm volatile(
        "mma.sync.aligned.m16n8k16.row.col.f32.bf16.bf16.f32 "
        "{%0,%1,%2,%3}, {%4,%5,%6,%7}, {%8,%9}, {%0,%1,%2,%3};"
        : "+f"(d[0]), "+f"(d[1]), "+f"(d[2]), "+f"(d[3])
        : "r"(a[0]), "r"(a[1]), "r"(a[2]), "r"(a[3]), "r"(b0), "r"(b1));
}

// ---------------- prep kernel: fold x -> bf16 patches (K-major, 96 rows) ----------------
// g_Bmat[c][k][m] = bf16( x[c, (m/576)*9 + k/9, (m%576)*9 + k%9] ), k<81 else 0
__global__ void build_b_kernel(const float* __restrict__ x) {
    int idx = blockIdx.x * blockDim.x + threadIdx.x;  // 6912*256 = 4*96*4608
    int m = idx % LL;
    int k = (idx / LL) % BNROWS;
    int c = idx / (LL * BNROWS);
    float v = 0.0f;
    if (k < 81) {
        int bi = m / NW, bj = m % NW;
        int ki = k / 9,  kj = k % 9;
        v = x[(size_t)c * XCH + (size_t)(bi * 9 + ki) * WPITCH + (bj * 9 + kj)];
    }
    g_Bmat[idx] = __float2bfloat16(v);
}

// ---------------- main fused kernel ----------------
__global__ void __launch_bounds__(256, 1) cross_head_main(
    const float* __restrict__ attn,
    const float* __restrict__ x,
    float* __restrict__ out)
{
    extern __shared__ char smem[];
    const uint32_t sbase = smem_to_u32(smem);
    const int tid  = threadIdx.x;
    const int wid  = tid >> 5;
    const int lane = tid & 31;
    const int c    = blockIdx.x / NBLK_M;
    const int mb   = blockIdx.x % NBLK_M;

    // warp tile: 4 m-groups x 2 n-groups; each warp does m32 x n48
    const int mbase = (wid >> 1) * 32;
    const int nbase = (wid & 1) * 48;

    // ---- producer addressing ----
    const int row  = tid >> 1;                 // 0..127
    const int half = tid & 1;                  // 32-col half of 64-chunk
    const float* gA = attn + ((size_t)c * LL + (size_t)(mb * TM + row)) * LL + half * 32;
    const __nv_bfloat16* gB = g_Bmat + (size_t)c * BNROWS * LL;

    // B producer indices (3 uint4 per thread per chunk)
    int brow_[3], bcol_[3];
    uint32_t bsw_[3];
    #pragma unroll
    for (int j = 0; j < 3; j++) {
        int idx = tid + j * 256;               // 0..767
        brow_[j] = idx >> 3;
        bcol_[j] = (idx & 7) * 8;              // bf16 col
        uint32_t off = (uint32_t)(brow_[j] * 128 + bcol_[j] * 2);
        bsw_[j] = off ^ (((uint32_t)brow_[j] & 7u) << 4);
    }
    // A producer swizzled base within a buffer
    const uint32_t asw_row = (uint32_t)(row * 128) ;
    const uint32_t asw_xor = ((uint32_t)row & 7u) << 4;

    // ---- ldmatrix lane addressing (per thread, fixed) ----
    // A frags (x4): grp = lane>>3: row += (grp&1)*8, colb += (grp>>1)*16
    const int la_row = (lane & 7) + ((lane >> 3) & 1) * 8;
    const int la_col = (lane >> 4) * 16;                       // byte
    int aRowFull[2]; uint32_t aBase[2], aXor[2];
    #pragma unroll
    for (int mi = 0; mi < 2; mi++) {
        aRowFull[mi] = mbase + 16 * mi + la_row;
        aBase[mi] = (uint32_t)(aRowFull[mi] * 128);
        aXor[mi]  = ((uint32_t)aRowFull[mi] & 7u) << 4;
    }
    // B frags (x4 covers n16 x k16): grp: n += (grp>>1)*8, colb += (grp&1)*16
    const int lb_n   = (lane & 7) + (lane >> 4) * 8;
    const int lb_col = ((lane >> 3) & 1) * 16;                 // byte
    int bNFull[3]; uint32_t bBase[3], bXor[3];
    #pragma unroll
    for (int nj2 = 0; nj2 < 3; nj2++) {
        bNFull[nj2] = nbase + 16 * nj2 + lb_n;
        bBase[nj2] = (uint32_t)(bNFull[nj2] * 128);
        bXor[nj2]  = ((uint32_t)bNFull[nj2] & 7u) << 4;
    }

    float acc[2][6][4];
    #pragma unroll
    for (int mi = 0; mi < 2; mi++)
        #pragma unroll
        for (int nj = 0; nj < 6; nj++)
            #pragma unroll
            for (int r = 0; r < 4; r++) acc[mi][nj][r] = 0.0f;

    // ---- prefetch chunk 0 ----
    float4 ra[8]; uint4 rb[3];
    {
        const float4* pa = reinterpret_cast<const float4*>(gA);
        #pragma unroll
        for (int i = 0; i < 8; i++) ra[i] = __ldcs(pa + i);
        #pragma unroll
        for (int j = 0; j < 3; j++)
            rb[j] = *reinterpret_cast<const uint4*>(gB + (size_t)brow_[j] * LL + bcol_[j]);
    }

    int cnt = 0;
    for (int ch = 0; ch < NCHUNKS; ch++) {
        const int buf = ch & 1;
        char* sa = smem + SM_A(buf);
        char* sb = smem + SM_B(buf);

        // ---- STS current chunk (count nz + convert on the way) ----
        #pragma unroll
        for (int i = 0; i < 8; i++) {
            float4 v = ra[i];
            cnt += (v.x != 0.0f) + (v.y != 0.0f) + (v.z != 0.0f) + (v.w != 0.0f);
            uint32_t p0, p1;
            asm("cvt.rn.bf16x2.f32 %0, %1, %2;" : "=r"(p0) : "f"(v.y), "f"(v.x));
            asm("cvt.rn.bf16x2.f32 %0, %1, %2;" : "=r"(p1) : "f"(v.w), "f"(v.z));
            uint32_t boff = (uint32_t)(half * 64 + i * 8);
            uint32_t sw = asw_row + (boff ^ asw_xor);
            *reinterpret_cast<uint2*>(sa + sw) = make_uint2(p0, p1);
        }
        #pragma unroll
        for (int j = 0; j < 3; j++)
            *reinterpret_cast<uint4*>(sb + bsw_[j]) = rb[j];

        __syncthreads();

        // ---- prefetch next chunk (overlaps compute) ----
        if (ch + 1 < NCHUNKS) {
            const float4* pa = reinterpret_cast<const float4*>(gA + (ch + 1) * KC);
            #pragma unroll
            for (int i = 0; i < 8; i++) ra[i] = __ldcs(pa + i);
            #pragma unroll
            for (int j = 0; j < 3; j++)
                rb[j] = *reinterpret_cast<const uint4*>(
                    gB + (size_t)brow_[j] * LL + (ch + 1) * KC + bcol_[j]);
        }

        // ---- compute chunk from smem ----
        const uint32_t saA = sbase + (uint32_t)SM_A(buf);
        const uint32_t saB = sbase + (uint32_t)SM_B(buf);
        #pragma unroll
        for (int ks = 0; ks < 4; ks++) {
            const uint32_t kb = (uint32_t)(ks * 32);   // byte offset of k-step
            uint32_t afr[2][4];
            #pragma unroll
            for (int mi = 0; mi < 2; mi++)
                ldmx4(afr[mi], saA + aBase[mi] + ((kb + (uint32_t)la_col) ^ aXor[mi]));
            uint32_t bfr[3][4];
            #pragma unroll
            for (int nj2 = 0; nj2 < 3; nj2++)
                ldmx4(bfr[nj2], saB + bBase[nj2] + ((kb + (uint32_t)lb_col) ^ bXor[nj2]));
            #pragma unroll
            for (int mi = 0; mi < 2; mi++)
                #pragma unroll
                for (int nj = 0; nj < 6; nj++)
                    mma16816(acc[mi][nj], afr[mi],
                             bfr[nj >> 1][(nj & 1) * 2], bfr[nj >> 1][(nj & 1) * 2 + 1]);
        }
        __syncthreads();
    }

    // ---- nz: combine the two half-row counts ----
    int other = __shfl_xor_sync(0xFFFFFFFFu, cnt, 1);
    if (half == 0)
        reinterpret_cast<float*>(smem + SM_NZ)[row] = (float)(cnt + other);
    __syncthreads();

    // ---- epilogue: scale by 1/nz, fold, corr*x + x, leaky relu ----
    const float* snz = reinterpret_cast<const float*>(smem + SM_NZ);
    #pragma unroll
    for (int mi = 0; mi < 2; mi++) {
        #pragma unroll
        for (int hr = 0; hr < 2; hr++) {
            const int m = mbase + 16 * mi + (lane >> 2) + 8 * hr;
            const float inv = 1.0f / (snz[m] + 1e-5f);
            const int l  = mb * TM + m;
            const int bi = l / NW, bj = l % NW;
            const size_t base = (size_t)c * XCH + (size_t)(bi * 9) * WPITCH + (size_t)(bj * 9);
            const float* xp = x + base;
            float* op = out + base;
            #pragma unroll
            for (int nj = 0; nj < 6; nj++) {
                #pragma unroll
                for (int e = 0; e < 2; e++) {
                    const int n = nbase + 8 * nj + 2 * (lane & 3) + e;
                    if (n < 81) {
                        const int ki = n / 9, kj = n % 9;
                        const float a  = acc[mi][nj][hr * 2 + e] * inv;
                        const float xv = xp[ki * WPITCH + kj];
                        const float o  = fmaf(a, xv, xv);
                        op[ki * WPITCH + kj] = (o >= 0.0f) ? o : 0.2f * o;
                    }
                }
            }
        }
    }
}

// ---------------- launch ----------------
extern "C" void kernel_launch(void* const* d_in, const int* in_sizes, int n_in,
                              void* d_out, int out_size) {
    const float* x;
    const float* attn;
    if (in_sizes[0] == 1492992) {           // x is 1*4*72*72*72
        x = (const float*)d_in[0];
        attn = (const float*)d_in[1];
    } else {
        x = (const float*)d_in[1];
        attn = (const float*)d_in[0];
    }
    cudaFuncSetAttribute(cross_head_main,
                         cudaFuncAttributeMaxDynamicSharedMemorySize, SMEM_BYTES);
    build_b_kernel<<<6912, 256>>>(x);       // 6912*256 == 4*96*4608
    cross_head_main<<<NCH * NBLK_M, 256, SMEM_BYTES>>>(attn, x, (float*)d_out);
}

// round 3
// speedup vs baseline: 1.7437x; 1.7437x over previous
#include <cuda_runtime.h>
#include <cuda_bf16.h>
#include <cstdint>

// ---------------- problem constants ----------------
#define NCH      4
#define LL       4608          // L = nH*nW
#define NW       576           // nW
#define TM       128           // M tile (attn rows per CTA)
#define KC       64            // bf16 K elements per pipeline chunk
#define NCHUNKS  72            // 4608 / 64
#define BNROWS   96            // N padded (81 -> 96)
#define WPITCH   5184          // 72*72
#define XCH      373248        // 72*5184 elements per channel
#define NBLK_M   36            // 4608/128
#define PITCH    144           // padded row pitch (bytes): conflict-free, no swizzle

// ---------------- smem layout (bytes) ----------------
// nz:   [0, 512)            128 floats
// A(s): 512   + s*18432     128 rows x 144B
// B(s): 37376 + s*13824      96 rows x 144B
#define SM_NZ       0
#define SM_A(s)     (512   + (s)*18432)
#define SM_B(s)     (37376 + (s)*13824)
#define SMEM_BYTES  65024

// ---------------- scratch: patches bf16, K-major, padded to 96 rows ----------------
__device__ __nv_bfloat16 g_Bmat[(size_t)NCH * BNROWS * LL];

__device__ __forceinline__ uint32_t smem_to_u32(const void* p) {
    uint32_t a;
    asm("{ .reg .u64 t; cvta.to.shared.u64 t, %1; cvt.u32.u64 %0, t; }" : "=r"(a) : "l"(p));
    return a;
}

__device__ __forceinline__ void ldmx4(uint32_t* r, uint32_t addr) {
    asm volatile("ldmatrix.sync.aligned.m8n8.x4.shared.b16 {%0,%1,%2,%3}, [%4];"
                 : "=r"(r[0]), "=r"(r[1]), "=r"(r[2]), "=r"(r[3]) : "r"(addr));
}

__device__ __forceinline__ void mma16816(float* d, const uint32_t* a,
                                         uint32_t b0, uint32_t b1) {
    asm volatile(
        "mma.sync.aligned.m16n8k16.row.col.f32.bf16.bf16.f32 "
        "{%0,%1,%2,%3}, {%4,%5,%6,%7}, {%8,%9}, {%0,%1,%2,%3};"
        : "+f"(d[0]), "+f"(d[1]), "+f"(d[2]), "+f"(d[3])
        : "r"(a[0]), "r"(a[1]), "r"(a[2]), "r"(a[3]), "r"(b0), "r"(b1));
}

__device__ __forceinline__ uint4 ldg_cg_v4(const void* p) {
    uint4 v;
    asm volatile("ld.global.cg.v4.u32 {%0,%1,%2,%3}, [%4];"
                 : "=r"(v.x), "=r"(v.y), "=r"(v.z), "=r"(v.w) : "l"(p));
    return v;
}

// ---------------- prep kernel: fold x -> bf16 patches (K-major, 96 rows) ----------------
// g_Bmat[c][k][m] = bf16( x[c, (m/576)*9 + k/9, (m%576)*9 + k%9] ), k<81 else 0
__global__ void build_b_kernel(const float* __restrict__ x) {
    int idx = blockIdx.x * blockDim.x + threadIdx.x;  // 6912*256 = 4*96*4608
    int m = idx % LL;
    int k = (idx / LL) % BNROWS;
    int c = idx / (LL * BNROWS);
    float v = 0.0f;
    if (k < 81) {
        int bi = m / NW, bj = m % NW;
        int ki = k / 9,  kj = k % 9;
        v = x[(size_t)c * XCH + (size_t)(bi * 9 + ki) * WPITCH + (bj * 9 + kj)];
    }
    g_Bmat[idx] = __float2bfloat16(v);
}

// ---------------- main fused kernel ----------------
__global__ void __launch_bounds__(256, 1) cross_head_main(
    const float* __restrict__ attn,
    const float* __restrict__ x,
    float* __restrict__ out)
{
    extern __shared__ char smem[];
    const uint32_t sbase = smem_to_u32(smem);
    const int tid  = threadIdx.x;
    const int wid  = tid >> 5;
    const int lane = tid & 31;
    const int c    = blockIdx.x / NBLK_M;
    const int mb   = blockIdx.x % NBLK_M;

    // warp tile: 4 m-groups x 2 n-groups; each warp does m32 x n48
    const int mbase = (wid >> 1) * 32;
    const int nbase = (wid & 1) * 48;

    // ---- producer addressing: thread owns 32B (8 floats) x 4 rows per chunk ----
    const int r0  = tid >> 3;                  // 0..31; rows r0 + 32g
    const int seg = tid & 7;                   // 32B segment within 64-col chunk
    const float* gA[4];
    #pragma unroll
    for (int g = 0; g < 4; g++)
        gA[g] = attn + ((size_t)c * LL + (size_t)(mb * TM + r0 + 32 * g)) * LL + seg * 8;
    const __nv_bfloat16* gB = g_Bmat + (size_t)c * BNROWS * LL;

    // A STS addresses (pitch-144, conflict-free)
    uint32_t aSts[4];
    #pragma unroll
    for (int g = 0; g < 4; g++)
        aSts[g] = (uint32_t)((r0 + 32 * g) * PITCH + seg * 16);

    // B producer indices (3 uint4 per thread per chunk)
    int brow_[3], bcol_[3];
    uint32_t bSts[3];
    #pragma unroll
    for (int j = 0; j < 3; j++) {
        int idx = tid + j * 256;               // 0..767
        brow_[j] = idx >> 3;
        bcol_[j] = (idx & 7) * 8;              // bf16 col
        bSts[j]  = (uint32_t)(brow_[j] * PITCH + (idx & 7) * 16);
    }

    // ---- ldmatrix lane addressing (pitch-144, no xor) ----
    const int la_row = (lane & 7) + ((lane >> 3) & 1) * 8;
    const int la_col = (lane >> 4) * 16;                       // byte
    uint32_t aBase[2];
    #pragma unroll
    for (int mi = 0; mi < 2; mi++)
        aBase[mi] = (uint32_t)((mbase + 16 * mi + la_row) * PITCH) + (uint32_t)la_col;
    const int lb_n   = (lane & 7) + (lane >> 4) * 8;
    const int lb_col = ((lane >> 3) & 1) * 16;                 // byte
    uint32_t bBase[3];
    #pragma unroll
    for (int nj2 = 0; nj2 < 3; nj2++)
        bBase[nj2] = (uint32_t)((nbase + 16 * nj2 + lb_n) * PITCH) + (uint32_t)lb_col;

    float acc[2][6][4];
    #pragma unroll
    for (int mi = 0; mi < 2; mi++)
        #pragma unroll
        for (int nj = 0; nj < 6; nj++)
            #pragma unroll
            for (int r = 0; r < 4; r++) acc[mi][nj][r] = 0.0f;

    // ---- prefetch chunk 0 ----
    float4 ra[8]; uint4 rb[3];
    {
        #pragma unroll
        for (int g = 0; g < 4; g++) {
            const float4* pa = reinterpret_cast<const float4*>(gA[g]);
            ra[2 * g]     = __ldcs(pa);
            ra[2 * g + 1] = __ldcs(pa + 1);
        }
        #pragma unroll
        for (int j = 0; j < 3; j++)
            rb[j] = ldg_cg_v4(gB + (size_t)brow_[j] * LL + bcol_[j]);
    }

    int cnt[4] = {0, 0, 0, 0};
    for (int ch = 0; ch < NCHUNKS; ch++) {
        const int buf = ch & 1;
        char* sa = smem + SM_A(buf);
        char* sb = smem + SM_B(buf);

        // ---- STS current chunk (count nz + convert on the way) ----
        #pragma unroll
        for (int g = 0; g < 4; g++) {
            float4 v0 = ra[2 * g], v1 = ra[2 * g + 1];
            cnt[g] += (v0.x != 0.0f) + (v0.y != 0.0f) + (v0.z != 0.0f) + (v0.w != 0.0f)
                    + (v1.x != 0.0f) + (v1.y != 0.0f) + (v1.z != 0.0f) + (v1.w != 0.0f);
            uint4 p;
            asm("cvt.rn.bf16x2.f32 %0, %1, %2;" : "=r"(p.x) : "f"(v0.y), "f"(v0.x));
            asm("cvt.rn.bf16x2.f32 %0, %1, %2;" : "=r"(p.y) : "f"(v0.w), "f"(v0.z));
            asm("cvt.rn.bf16x2.f32 %0, %1, %2;" : "=r"(p.z) : "f"(v1.y), "f"(v1.x));
            asm("cvt.rn.bf16x2.f32 %0, %1, %2;" : "=r"(p.w) : "f"(v1.w), "f"(v1.z));
            *reinterpret_cast<uint4*>(sa + aSts[g]) = p;
        }
        #pragma unroll
        for (int j = 0; j < 3; j++)
            *reinterpret_cast<uint4*>(sb + bSts[j]) = rb[j];

        __syncthreads();

        // ---- prefetch next chunk (overlaps compute) ----
        if (ch + 1 < NCHUNKS) {
            #pragma unroll
            for (int g = 0; g < 4; g++) {
                const float4* pa = reinterpret_cast<const float4*>(gA[g] + (ch + 1) * KC);
                ra[2 * g]     = __ldcs(pa);
                ra[2 * g + 1] = __ldcs(pa + 1);
            }
            #pragma unroll
            for (int j = 0; j < 3; j++)
                rb[j] = ldg_cg_v4(gB + (size_t)brow_[j] * LL + (ch + 1) * KC + bcol_[j]);
        }

        // ---- compute chunk from smem ----
        const uint32_t saA = sbase + (uint32_t)SM_A(buf);
        const uint32_t saB = sbase + (uint32_t)SM_B(buf);
        #pragma unroll
        for (int ks = 0; ks < 4; ks++) {
            const uint32_t kb = (uint32_t)(ks * 32);   // byte offset of k-step
            uint32_t afr[2][4];
            #pragma unroll
            for (int mi = 0; mi < 2; mi++)
                ldmx4(afr[mi], saA + aBase[mi] + kb);
            uint32_t bfr[3][4];
            #pragma unroll
            for (int nj2 = 0; nj2 < 3; nj2++)
                ldmx4(bfr[nj2], saB + bBase[nj2] + kb);
            #pragma unroll
            for (int mi = 0; mi < 2; mi++)
                #pragma unroll
                for (int nj = 0; nj < 6; nj++)
                    mma16816(acc[mi][nj], afr[mi],
                             bfr[nj >> 1][(nj & 1) * 2], bfr[nj >> 1][(nj & 1) * 2 + 1]);
        }
        __syncthreads();
    }

    // ---- nz: reduce 8 lanes (same row group) per row ----
    #pragma unroll
    for (int g = 0; g < 4; g++) {
        int v = cnt[g];
        v += __shfl_xor_sync(0xFFFFFFFFu, v, 1);
        v += __shfl_xor_sync(0xFFFFFFFFu, v, 2);
        v += __shfl_xor_sync(0xFFFFFFFFu, v, 4);
        if (seg == 0)
            reinterpret_cast<float*>(smem + SM_NZ)[r0 + 32 * g] = (float)v;
    }
    __syncthreads();

    // ---- epilogue: scale by 1/nz, fold, corr*x + x, leaky relu ----
    const float* snz = reinterpret_cast<const float*>(smem + SM_NZ);
    #pragma unroll
    for (int mi = 0; mi < 2; mi++) {
        #pragma unroll
        for (int hr = 0; hr < 2; hr++) {
            const int m = mbase + 16 * mi + (lane >> 2) + 8 * hr;
            const float inv = 1.0f / (snz[m] + 1e-5f);
            const int l  = mb * TM + m;
            const int bi = l / NW, bj = l % NW;
            const size_t base = (size_t)c * XCH + (size_t)(bi * 9) * WPITCH + (size_t)(bj * 9);
            const float* xp = x + base;
            float* op = out + base;
            #pragma unroll
            for (int nj = 0; nj < 6; nj++) {
                #pragma unroll
                for (int e = 0; e < 2; e++) {
                    const int n = nbase + 8 * nj + 2 * (lane & 3) + e;
                    if (n < 81) {
                        const int ki = n / 9, kj = n % 9;
                        const float a  = acc[mi][nj][hr * 2 + e] * inv;
                        const float xv = xp[ki * WPITCH + kj];
                        const float o  = fmaf(a, xv, xv);
                        op[ki * WPITCH + kj] = (o >= 0.0f) ? o : 0.2f * o;
                    }
                }
            }
        }
    }
}

// ---------------- launch ----------------
extern "C" void kernel_launch(void* const* d_in, const int* in_sizes, int n_in,
                              void* d_out, int out_size) {
    const float* x;
    const float* attn;
    if (in_sizes[0] == 1492992) {           // x is 1*4*72*72*72
        x = (const float*)d_in[0];
        attn = (const float*)d_in[1];
    } else {
        x = (const float*)d_in[1];
        attn = (const float*)d_in[0];
    }
    cudaFuncSetAttribute(cross_head_main,
                         cudaFuncAttributeMaxDynamicSharedMemorySize, SMEM_BYTES);
    build_b_kernel<<<6912, 256>>>(x);       // 6912*256 == 4*96*4608
    cross_head_main<<<NCH * NBLK_M, 256, SMEM_BYTES>>>(attn, x, (float*)d_out);
}

// round 4
// speedup vs baseline: 1.8276x; 1.0481x over previous
#include <cuda_runtime.h>
#include <cuda_bf16.h>
#include <cstdint>

// ---------------- problem constants ----------------
#define NCH      4
#define LL       4608          // L = nH*nW
#define NW       576           // nW
#define TM       64            // M tile (attn rows per CTA)
#define KC       64            // bf16 K elements per pipeline chunk
#define NCHUNKS  72            // 4608 / 64
#define BNROWS   96            // N padded (81 -> 96)
#define WPITCH   5184          // 72*72
#define XCH      373248        // 72*5184 elements per channel
#define NBLK_M   72            // 4608/64
#define PITCH    144           // padded row pitch (bytes): conflict-free, no swizzle

// ---------------- smem layout (bytes) ----------------
// nz:   [0, 256)            64 floats
// A(s): 512   + s*9216      64 rows x 144B
// B(s): 18944 + s*13824     96 rows x 144B
#define SM_NZ       0
#define SM_A(s)     (512   + (s)*9216)
#define SM_B(s)     (18944 + (s)*13824)
#define SMEM_BYTES  46592

// ---------------- scratch: patches bf16, K-major, padded to 96 rows ----------------
__device__ __nv_bfloat16 g_Bmat[(size_t)NCH * BNROWS * LL];

__device__ __forceinline__ uint32_t smem_to_u32(const void* p) {
    uint32_t a;
    asm("{ .reg .u64 t; cvta.to.shared.u64 t, %1; cvt.u32.u64 %0, t; }" : "=r"(a) : "l"(p));
    return a;
}

__device__ __forceinline__ void ldmx4(uint32_t* r, uint32_t addr) {
    asm volatile("ldmatrix.sync.aligned.m8n8.x4.shared.b16 {%0,%1,%2,%3}, [%4];"
                 : "=r"(r[0]), "=r"(r[1]), "=r"(r[2]), "=r"(r[3]) : "r"(addr));
}

__device__ __forceinline__ void mma16816(float* d, const uint32_t* a,
                                         uint32_t b0, uint32_t b1) {
    asm volatile(
        "mma.sync.aligned.m16n8k16.row.col.f32.bf16.bf16.f32 "
        "{%0,%1,%2,%3}, {%4,%5,%6,%7}, {%8,%9}, {%0,%1,%2,%3};"
        : "+f"(d[0]), "+f"(d[1]), "+f"(d[2]), "+f"(d[3])
        : "r"(a[0]), "r"(a[1]), "r"(a[2]), "r"(a[3]), "r"(b0), "r"(b1));
}

__device__ __forceinline__ uint4 ldg_cg_v4(const void* p) {
    uint4 v;
    asm volatile("ld.global.cg.v4.u32 {%0,%1,%2,%3}, [%4];"
                 : "=r"(v.x), "=r"(v.y), "=r"(v.z), "=r"(v.w) : "l"(p));
    return v;
}

// ---------------- prep kernel: fold x -> bf16 patches (K-major, 96 rows) ----------------
// g_Bmat[c][k][m] = bf16( x[c, (m/576)*9 + k/9, (m%576)*9 + k%9] ), k<81 else 0
__global__ void build_b_kernel(const float* __restrict__ x) {
    int idx = blockIdx.x * blockDim.x + threadIdx.x;  // 6912*256 = 4*96*4608
    int m = idx % LL;
    int k = (idx / LL) % BNROWS;
    int c = idx / (LL * BNROWS);
    float v = 0.0f;
    if (k < 81) {
        int bi = m / NW, bj = m % NW;
        int ki = k / 9,  kj = k % 9;
        v = x[(size_t)c * XCH + (size_t)(bi * 9 + ki) * WPITCH + (bj * 9 + kj)];
    }
    g_Bmat[idx] = __float2bfloat16(v);
}

// ---------------- main fused kernel ----------------
__global__ void __launch_bounds__(256, 2) cross_head_main(
    const float* __restrict__ attn,
    const float* __restrict__ x,
    float* __restrict__ out)
{
    extern __shared__ char smem[];
    const uint32_t sbase = smem_to_u32(smem);
    const int tid  = threadIdx.x;
    const int wid  = tid >> 5;
    const int lane = tid & 31;
    const int c    = blockIdx.x / NBLK_M;
    const int mb   = blockIdx.x % NBLK_M;

    // warp tile: 4 m-groups x 2 n-groups; each warp does m16 x n48
    const int mbase = (wid >> 1) * 16;
    const int nbase = (wid & 1) * 48;

    // ---- producer addressing: thread owns 32B (8 floats) x 2 rows per chunk ----
    const int r0  = tid >> 3;                  // 0..31; rows r0, r0+32
    const int seg = tid & 7;                   // 32B segment within 64-col chunk
    const float* gA[2];
    #pragma unroll
    for (int g = 0; g < 2; g++)
        gA[g] = attn + ((size_t)c * LL + (size_t)(mb * TM + r0 + 32 * g)) * LL + seg * 8;
    const __nv_bfloat16* gB = g_Bmat + (size_t)c * BNROWS * LL;

    // A STS addresses (pitch-144, conflict-free)
    uint32_t aSts[2];
    #pragma unroll
    for (int g = 0; g < 2; g++)
        aSts[g] = (uint32_t)((r0 + 32 * g) * PITCH + seg * 16);

    // B producer indices (3 uint4 per thread per chunk)
    int brow_[3], bcol_[3];
    uint32_t bSts[3];
    #pragma unroll
    for (int j = 0; j < 3; j++) {
        int idx = tid + j * 256;               // 0..767
        brow_[j] = idx >> 3;
        bcol_[j] = (idx & 7) * 8;              // bf16 col
        bSts[j]  = (uint32_t)(brow_[j] * PITCH + (idx & 7) * 16);
    }

    // ---- ldmatrix lane addressing (pitch-144, no xor) ----
    const int la_row = (lane & 7) + ((lane >> 3) & 1) * 8;
    const int la_col = (lane >> 4) * 16;                       // byte
    const uint32_t aBase = (uint32_t)((mbase + la_row) * PITCH) + (uint32_t)la_col;
    const int lb_n   = (lane & 7) + (lane >> 4) * 8;
    const int lb_col = ((lane >> 3) & 1) * 16;                 // byte
    uint32_t bBase[3];
    #pragma unroll
    for (int nj2 = 0; nj2 < 3; nj2++)
        bBase[nj2] = (uint32_t)((nbase + 16 * nj2 + lb_n) * PITCH) + (uint32_t)lb_col;

    float acc[6][4];
    #pragma unroll
    for (int nj = 0; nj < 6; nj++)
        #pragma unroll
        for (int r = 0; r < 4; r++) acc[nj][r] = 0.0f;

    // ---- prefetch chunk 0 ----
    float4 ra[4]; uint4 rb[3];
    {
        #pragma unroll
        for (int g = 0; g < 2; g++) {
            const float4* pa = reinterpret_cast<const float4*>(gA[g]);
            ra[2 * g]     = __ldcs(pa);
            ra[2 * g + 1] = __ldcs(pa + 1);
        }
        #pragma unroll
        for (int j = 0; j < 3; j++)
            rb[j] = ldg_cg_v4(gB + (size_t)brow_[j] * LL + bcol_[j]);
    }

    int cnt[2] = {0, 0};
    for (int ch = 0; ch < NCHUNKS; ch++) {
        const int buf = ch & 1;
        char* sa = smem + SM_A(buf);
        char* sb = smem + SM_B(buf);

        // ---- STS current chunk (count nz + convert on the way) ----
        #pragma unroll
        for (int g = 0; g < 2; g++) {
            float4 v0 = ra[2 * g], v1 = ra[2 * g + 1];
            cnt[g] += (v0.x != 0.0f) + (v0.y != 0.0f) + (v0.z != 0.0f) + (v0.w != 0.0f)
                    + (v1.x != 0.0f) + (v1.y != 0.0f) + (v1.z != 0.0f) + (v1.w != 0.0f);
            uint4 p;
            asm("cvt.rn.bf16x2.f32 %0, %1, %2;" : "=r"(p.x) : "f"(v0.y), "f"(v0.x));
            asm("cvt.rn.bf16x2.f32 %0, %1, %2;" : "=r"(p.y) : "f"(v0.w), "f"(v0.z));
            asm("cvt.rn.bf16x2.f32 %0, %1, %2;" : "=r"(p.z) : "f"(v1.y), "f"(v1.x));
            asm("cvt.rn.bf16x2.f32 %0, %1, %2;" : "=r"(p.w) : "f"(v1.w), "f"(v1.z));
            *reinterpret_cast<uint4*>(sa + aSts[g]) = p;
        }
        #pragma unroll
        for (int j = 0; j < 3; j++)
            *reinterpret_cast<uint4*>(sb + bSts[j]) = rb[j];

        __syncthreads();

        // ---- prefetch next chunk (overlaps compute) ----
        if (ch + 1 < NCHUNKS) {
            #pragma unroll
            for (int g = 0; g < 2; g++) {
                const float4* pa = reinterpret_cast<const float4*>(gA[g] + (ch + 1) * KC);
                ra[2 * g]     = __ldcs(pa);
                ra[2 * g + 1] = __ldcs(pa + 1);
            }
            #pragma unroll
            for (int j = 0; j < 3; j++)
                rb[j] = ldg_cg_v4(gB + (size_t)brow_[j] * LL + (ch + 1) * KC + bcol_[j]);
        }

        // ---- compute chunk from smem ----
        const uint32_t saA = sbase + (uint32_t)SM_A(buf);
        const uint32_t saB = sbase + (uint32_t)SM_B(buf);
        #pragma unroll
        for (int ks = 0; ks < 4; ks++) {
            const uint32_t kb = (uint32_t)(ks * 32);   // byte offset of k-step
            uint32_t afr[4];
            ldmx4(afr, saA + aBase + kb);
            uint32_t bfr[3][4];
            #pragma unroll
            for (int nj2 = 0; nj2 < 3; nj2++)
                ldmx4(bfr[nj2], saB + bBase[nj2] + kb);
            #pragma unroll
            for (int nj = 0; nj < 6; nj++)
                mma16816(acc[nj], afr,
                         bfr[nj >> 1][(nj & 1) * 2], bfr[nj >> 1][(nj & 1) * 2 + 1]);
        }
        __syncthreads();
    }

    // ---- nz: reduce 8 lanes (same row group) per row ----
    #pragma unroll
    for (int g = 0; g < 2; g++) {
        int v = cnt[g];
        v += __shfl_xor_sync(0xFFFFFFFFu, v, 1);
        v += __shfl_xor_sync(0xFFFFFFFFu, v, 2);
        v += __shfl_xor_sync(0xFFFFFFFFu, v, 4);
        if (seg == 0)
            reinterpret_cast<float*>(smem + SM_NZ)[r0 + 32 * g] = (float)v;
    }
    __syncthreads();

    // ---- epilogue: scale by 1/nz, fold, corr*x + x, leaky relu ----
    const float* snz = reinterpret_cast<const float*>(smem + SM_NZ);
    #pragma unroll
    for (int hr = 0; hr < 2; hr++) {
        const int m = mbase + (lane >> 2) + 8 * hr;
        const float inv = 1.0f / (snz[m] + 1e-5f);
        const int l  = mb * TM + m;
        const int bi = l / NW, bj = l % NW;
        const size_t base = (size_t)c * XCH + (size_t)(bi * 9) * WPITCH + (size_t)(bj * 9);
        const float* xp = x + base;
        float* op = out + base;
        #pragma unroll
        for (int nj = 0; nj < 6; nj++) {
            #pragma unroll
            for (int e = 0; e < 2; e++) {
                const int n = nbase + 8 * nj + 2 * (lane & 3) + e;
                if (n < 81) {
                    const int ki = n / 9, kj = n % 9;
                    const float a  = acc[nj][hr * 2 + e] * inv;
                    const float xv = xp[ki * WPITCH + kj];
                    const float o  = fmaf(a, xv, xv);
                    op[ki * WPITCH + kj] = (o >= 0.0f) ? o : 0.2f * o;
                }
            }
        }
    }
}

// ---------------- launch ----------------
extern "C" void kernel_launch(void* const* d_in, const int* in_sizes, int n_in,
                              void* d_out, int out_size) {
    const float* x;
    const float* attn;
    if (in_sizes[0] == 1492992) {           // x is 1*4*72*72*72
        x = (const float*)d_in[0];
        attn = (const float*)d_in[1];
    } else {
        x = (const float*)d_in[1];
        attn = (const float*)d_in[0];
    }
    cudaFuncSetAttribute(cross_head_main,
                         cudaFuncAttributeMaxDynamicSharedMemorySize, SMEM_BYTES);
    build_b_kernel<<<6912, 256>>>(x);       // 6912*256 == 4*96*4608
    cross_head_main<<<NCH * NBLK_M, 256, SMEM_BYTES>>>(attn, x, (float*)d_out);
}

// round 5
// speedup vs baseline: 1.8720x; 1.0243x over previous
#include <cuda_runtime.h>
#include <cuda_bf16.h>
#include <cstdint>

// ---------------- problem constants ----------------
#define NCH      4
#define LL       4608          // L = nH*nW
#define NW       576           // nW
#define TM       64            // M tile (attn rows per CTA)
#define KC       64            // bf16 K elements per pipeline chunk
#define NCHUNKS  72            // 4608 / 64
#define BNROWS   96            // N padded (81 -> 96)
#define WPITCH   5184          // 72*72
#define XCH      373248        // 72*5184 elements per channel
#define NBLK_M   72            // 4608/64
#define PITCH    144           // padded row pitch (bytes): conflict-free, no swizzle

// ---------------- smem layout (bytes) ----------------
#define SM_NZ       0
#define SM_A(s)     (512   + (s)*9216)      // 64 rows x 144B
#define SM_B(s)     (18944 + (s)*13824)     // 96 rows x 144B
#define SMEM_BYTES  46592

// ---------------- scratch: patches bf16, K-major, padded to 96 rows ----------------
__device__ __nv_bfloat16 g_Bmat[(size_t)NCH * BNROWS * LL];

__device__ __forceinline__ uint32_t smem_to_u32(const void* p) {
    uint32_t a;
    asm("{ .reg .u64 t; cvta.to.shared.u64 t, %1; cvt.u32.u64 %0, t; }" : "=r"(a) : "l"(p));
    return a;
}

__device__ __forceinline__ void ldmx4(uint32_t* r, uint32_t addr) {
    asm volatile("ldmatrix.sync.aligned.m8n8.x4.shared.b16 {%0,%1,%2,%3}, [%4];"
                 : "=r"(r[0]), "=r"(r[1]), "=r"(r[2]), "=r"(r[3]) : "r"(addr));
}
__device__ __forceinline__ void ldmx2(uint32_t* r, uint32_t addr) {
    asm volatile("ldmatrix.sync.aligned.m8n8.x2.shared.b16 {%0,%1}, [%2];"
                 : "=r"(r[0]), "=r"(r[1]) : "r"(addr));
}

__device__ __forceinline__ void mma16816(float* d, const uint32_t* a,
                                         uint32_t b0, uint32_t b1) {
    asm volatile(
        "mma.sync.aligned.m16n8k16.row.col.f32.bf16.bf16.f32 "
        "{%0,%1,%2,%3}, {%4,%5,%6,%7}, {%8,%9}, {%0,%1,%2,%3};"
        : "+f"(d[0]), "+f"(d[1]), "+f"(d[2]), "+f"(d[3])
        : "r"(a[0]), "r"(a[1]), "r"(a[2]), "r"(a[3]), "r"(b0), "r"(b1));
}

#define CP_ASYNC_CG(dst, src) \
    asm volatile("cp.async.cg.shared.global [%0], [%1], 16;" :: "r"(dst), "l"(src))
#define CP_COMMIT() asm volatile("cp.async.commit_group;" ::: "memory")
#define CP_WAIT(n)  asm volatile("cp.async.wait_group %0;" :: "n"(n) : "memory")

// ---------------- prep kernel: fold x -> bf16 patches (K-major, 96 rows) ----------------
__global__ void build_b_kernel(const float* __restrict__ x) {
    int idx = blockIdx.x * blockDim.x + threadIdx.x;  // 6912*256 = 4*96*4608
    int m = idx % LL;
    int k = (idx / LL) % BNROWS;
    int c = idx / (LL * BNROWS);
    float v = 0.0f;
    if (k < 81) {
        int bi = m / NW, bj = m % NW;
        int ki = k / 9,  kj = k % 9;
        v = x[(size_t)c * XCH + (size_t)(bi * 9 + ki) * WPITCH + (bj * 9 + kj)];
    }
    g_Bmat[idx] = __float2bfloat16(v);
}

// ---------------- main fused kernel ----------------
__global__ void __launch_bounds__(256, 2) cross_head_main(
    const float* __restrict__ attn,
    const float* __restrict__ x,
    float* __restrict__ out)
{
    extern __shared__ char smem[];
    const uint32_t sbase = smem_to_u32(smem);
    const int tid  = threadIdx.x;
    const int wid  = tid >> 5;
    const int lane = tid & 31;
    const int c    = blockIdx.x / NBLK_M;
    const int mb   = blockIdx.x % NBLK_M;

    // warp tile: 2 m-groups x 4 n-groups; each warp does m32 x n24
    const int mbase = (wid >> 2) * 32;
    const int nbase = (wid & 3) * 24;

    // ---- producer addressing: thread owns 32B (8 floats) x 2 rows per chunk ----
    const int r0  = tid >> 3;                  // 0..31; rows r0, r0+32
    const int seg = tid & 7;                   // 32B segment within 64-col chunk
    const float* gA[2];
    #pragma unroll
    for (int g = 0; g < 2; g++)
        gA[g] = attn + ((size_t)c * LL + (size_t)(mb * TM + r0 + 32 * g)) * LL + seg * 8;
    const __nv_bfloat16* gB = g_Bmat + (size_t)c * BNROWS * LL;

    // A STS addresses (pitch-144, conflict-free)
    uint32_t aSts[2];
    #pragma unroll
    for (int g = 0; g < 2; g++)
        aSts[g] = (uint32_t)((r0 + 32 * g) * PITCH + seg * 16);

    // B cp.async indices: 3 x 16B per thread per chunk (96 rows x 8 segs = 768)
    int brow_[3];
    uint32_t bSts[3];
    #pragma unroll
    for (int j = 0; j < 3; j++) {
        int idx = tid + j * 256;               // 0..767
        brow_[j] = idx >> 3;
        bSts[j]  = (uint32_t)(brow_[j] * PITCH + (idx & 7) * 16);
    }

    // ---- ldmatrix lane addressing (pitch-144, no xor) ----
    const int la_row = (lane & 7) + ((lane >> 3) & 1) * 8;
    const int la_col = (lane >> 4) * 16;                       // byte
    uint32_t aBase[2];
    #pragma unroll
    for (int mi = 0; mi < 2; mi++)
        aBase[mi] = (uint32_t)((mbase + 16 * mi + la_row) * PITCH) + (uint32_t)la_col;
    // B x4: covers n16 x k16 (lanes: n0-7/k0, n0-7/k16B, n8-15/k0, n8-15/k16B)
    const int lb_n   = (lane & 7) + (lane >> 4) * 8;
    const int lb_col = ((lane >> 3) & 1) * 16;                 // byte
    const uint32_t bBase4 = (uint32_t)((nbase + lb_n) * PITCH) + (uint32_t)lb_col;
    // B x2: covers n8 x k16 (lanes 0-15 supply addrs)
    const uint32_t bBase2 = (uint32_t)((nbase + 16 + (lane & 7)) * PITCH)
                          + (uint32_t)(((lane >> 3) & 1) * 16);

    float acc[2][3][4];
    #pragma unroll
    for (int mi = 0; mi < 2; mi++)
        #pragma unroll
        for (int nj = 0; nj < 3; nj++)
            #pragma unroll
            for (int r = 0; r < 4; r++) acc[mi][nj][r] = 0.0f;

    // ---- prefetch chunk 0: A to regs, B via cp.async ----
    float4 ra[4];
    {
        #pragma unroll
        for (int j = 0; j < 3; j++)
            CP_ASYNC_CG(sbase + SM_B(0) + bSts[j],
                        gB + (size_t)brow_[j] * LL + (tid & 7) * 8
                           + (size_t)(j * 256 & 7) * 0);  // seg from idx below
        CP_COMMIT();
        #pragma unroll
        for (int g = 0; g < 2; g++) {
            const float4* pa = reinterpret_cast<const float4*>(gA[g]);
            ra[2 * g]     = __ldcs(pa);
            ra[2 * g + 1] = __ldcs(pa + 1);
        }
    }

    int cnt[2] = {0, 0};
    for (int ch = 0; ch < NCHUNKS; ch++) {
        const int buf = ch & 1;
        char* sa = smem + SM_A(buf);

        // ---- STS current A chunk (count nz + convert on the way) ----
        #pragma unroll
        for (int g = 0; g < 2; g++) {
            float4 v0 = ra[2 * g], v1 = ra[2 * g + 1];
            cnt[g] += (v0.x != 0.0f) + (v0.y != 0.0f) + (v0.z != 0.0f) + (v0.w != 0.0f)
                    + (v1.x != 0.0f) + (v1.y != 0.0f) + (v1.z != 0.0f) + (v1.w != 0.0f);
            uint4 p;
            asm("cvt.rn.bf16x2.f32 %0, %1, %2;" : "=r"(p.x) : "f"(v0.y), "f"(v0.x));
            asm("cvt.rn.bf16x2.f32 %0, %1, %2;" : "=r"(p.y) : "f"(v0.w), "f"(v0.z));
            asm("cvt.rn.bf16x2.f32 %0, %1, %2;" : "=r"(p.z) : "f"(v1.y), "f"(v1.x));
            asm("cvt.rn.bf16x2.f32 %0, %1, %2;" : "=r"(p.w) : "f"(v1.w), "f"(v1.z));
            *reinterpret_cast<uint4*>(sa + aSts[g]) = p;
        }

        // ---- prefetch next chunk: B cp.async, A LDG ----
        if (ch + 1 < NCHUNKS) {
            #pragma unroll
            for (int j = 0; j < 3; j++) {
                int idx = tid + j * 256;
                CP_ASYNC_CG(sbase + SM_B(buf ^ 1) + bSts[j],
                            gB + (size_t)brow_[j] * LL + (ch + 1) * KC + (idx & 7) * 8);
            }
            CP_COMMIT();
            #pragma unroll
            for (int g = 0; g < 2; g++) {
                const float4* pa = reinterpret_cast<const float4*>(gA[g] + (ch + 1) * KC);
                ra[2 * g]     = __ldcs(pa);
                ra[2 * g + 1] = __ldcs(pa + 1);
            }
            CP_WAIT(1);      // B(ch) complete, B(ch+1) may be in flight
        } else {
            CP_WAIT(0);      // drain: B(ch) complete
        }
        __syncthreads();

        // ---- compute chunk from smem ----
        const uint32_t saA = sbase + (uint32_t)SM_A(buf);
        const uint32_t saB = sbase + (uint32_t)SM_B(buf);
        #pragma unroll
        for (int ks = 0; ks < 4; ks++) {
            const uint32_t kb = (uint32_t)(ks * 32);   // byte offset of k-step
            uint32_t afr[2][4];
            #pragma unroll
            for (int mi = 0; mi < 2; mi++)
                ldmx4(afr[mi], saA + aBase[mi] + kb);
            uint32_t bfr[6];
            ldmx4(bfr,     saB + bBase4 + kb);
            ldmx2(bfr + 4, saB + bBase2 + kb);
            #pragma unroll
            for (int mi = 0; mi < 2; mi++)
                #pragma unroll
                for (int nj = 0; nj < 3; nj++)
                    mma16816(acc[mi][nj], afr[mi], bfr[nj * 2], bfr[nj * 2 + 1]);
        }
        __syncthreads();
    }

    // ---- nz: reduce 8 lanes (same row group) per row ----
    #pragma unroll
    for (int g = 0; g < 2; g++) {
        int v = cnt[g];
        v += __shfl_xor_sync(0xFFFFFFFFu, v, 1);
        v += __shfl_xor_sync(0xFFFFFFFFu, v, 2);
        v += __shfl_xor_sync(0xFFFFFFFFu, v, 4);
        if (seg == 0)
            reinterpret_cast<float*>(smem + SM_NZ)[r0 + 32 * g] = (float)v;
    }
    __syncthreads();

    // ---- epilogue: scale by 1/nz, fold, corr*x + x, leaky relu ----
    const float* snz = reinterpret_cast<const float*>(smem + SM_NZ);
    #pragma unroll
    for (int mi = 0; mi < 2; mi++) {
        #pragma unroll
        for (int hr = 0; hr < 2; hr++) {
            const int m = mbase + 16 * mi + (lane >> 2) + 8 * hr;
            const float inv = 1.0f / (snz[m] + 1e-5f);
            const int l  = mb * TM + m;
            const int bi = l / NW, bj = l % NW;
            const size_t base = (size_t)c * XCH + (size_t)(bi * 9) * WPITCH + (size_t)(bj * 9);
            const float* xp = x + base;
            float* op = out + base;
            #pragma unroll
            for (int nj = 0; nj < 3; nj++) {
                #pragma unroll
                for (int e = 0; e < 2; e++) {
                    const int n = nbase + 8 * nj + 2 * (lane & 3) + e;
                    if (n < 81) {
                        const int ki = n / 9, kj = n % 9;
                        const float a  = acc[mi][nj][hr * 2 + e] * inv;
                        const float xv = xp[ki * WPITCH + kj];
                        const float o  = fmaf(a, xv, xv);
                        op[ki * WPITCH + kj] = (o >= 0.0f) ? o : 0.2f * o;
                    }
                }
            }
        }
    }
}

// ---------------- launch ----------------
extern "C" void kernel_launch(void* const* d_in, const int* in_sizes, int n_in,
                              void* d_out, int out_size) {
    const float* x;
    const float* attn;
    if (in_sizes[0] == 1492992) {           // x is 1*4*72*72*72
        x = (const float*)d_in[0];
        attn = (const float*)d_in[1];
    } else {
        x = (const float*)d_in[1];
        attn = (const float*)d_in[0];
    }
    cudaFuncSetAttribute(cross_head_main,
                         cudaFuncAttributeMaxDynamicSharedMemorySize, SMEM_BYTES);
    build_b_kernel<<<6912, 256>>>(x);       // 6912*256 == 4*96*4608
    cross_head_main<<<NCH * NBLK_M, 256, SMEM_BYTES>>>(attn, x, (float*)d_out);
}

// round 6
// speedup vs baseline: 1.9441x; 1.0386x over previous
#include <cuda_runtime.h>
#include <cuda_bf16.h>
#include <cstdint>

// ---------------- problem constants ----------------
#define NCH      4
#define LL       4608          // L = nH*nW
#define NW       576           // nW
#define TM       64            // M tile (attn rows per CTA)
#define KC       64            // bf16 K elements per pipeline chunk
#define NCHUNKS  72            // 4608 / 64
#define BNROWS   96            // N padded (81 -> 96)
#define WPITCH   5184          // 72*72
#define XCH      373248        // 72*5184 elements per channel
#define NBLK_M   72            // 4608/64
#define PITCH    144           // padded row pitch (bytes): conflict-free, no swizzle

// ---------------- smem layout (bytes), 3-stage ----------------
#define SM_NZ       0
#define SM_A(s)     (512   + (s)*9216)      // 64 rows x 144B, 3 stages
#define SM_B(s)     (28160 + (s)*13824)     // 96 rows x 144B, 3 stages
#define SMEM_BYTES  69632

// ---------------- scratch: patches bf16, K-major, padded to 96 rows ----------------
__device__ __nv_bfloat16 g_Bmat[(size_t)NCH * BNROWS * LL];

__device__ __forceinline__ uint32_t smem_to_u32(const void* p) {
    uint32_t a;
    asm("{ .reg .u64 t; cvta.to.shared.u64 t, %1; cvt.u32.u64 %0, t; }" : "=r"(a) : "l"(p));
    return a;
}

__device__ __forceinline__ void ldmx4(uint32_t* r, uint32_t addr) {
    asm volatile("ldmatrix.sync.aligned.m8n8.x4.shared.b16 {%0,%1,%2,%3}, [%4];"
                 : "=r"(r[0]), "=r"(r[1]), "=r"(r[2]), "=r"(r[3]) : "r"(addr));
}
__device__ __forceinline__ void ldmx2(uint32_t* r, uint32_t addr) {
    asm volatile("ldmatrix.sync.aligned.m8n8.x2.shared.b16 {%0,%1}, [%2];"
                 : "=r"(r[0]), "=r"(r[1]) : "r"(addr));
}

__device__ __forceinline__ void mma16816(float* d, const uint32_t* a,
                                         uint32_t b0, uint32_t b1) {
    asm volatile(
        "mma.sync.aligned.m16n8k16.row.col.f32.bf16.bf16.f32 "
        "{%0,%1,%2,%3}, {%4,%5,%6,%7}, {%8,%9}, {%0,%1,%2,%3};"
        : "+f"(d[0]), "+f"(d[1]), "+f"(d[2]), "+f"(d[3])
        : "r"(a[0]), "r"(a[1]), "r"(a[2]), "r"(a[3]), "r"(b0), "r"(b1));
}

#define CP_ASYNC_CG(dst, src) \
    asm volatile("cp.async.cg.shared.global [%0], [%1], 16;" :: "r"(dst), "l"(src))
#define CP_COMMIT() asm volatile("cp.async.commit_group;" ::: "memory")
#define CP_WAIT(n)  asm volatile("cp.async.wait_group %0;" :: "n"(n) : "memory")

// ---------------- prep kernel: fold x -> bf16 patches (K-major, 96 rows) ----------------
__global__ void build_b_kernel(const float* __restrict__ x) {
    int idx = blockIdx.x * blockDim.x + threadIdx.x;  // 6912*256 = 4*96*4608
    int m = idx % LL;
    int k = (idx / LL) % BNROWS;
    int c = idx / (LL * BNROWS);
    float v = 0.0f;
    if (k < 81) {
        int bi = m / NW, bj = m % NW;
        int ki = k / 9,  kj = k % 9;
        v = x[(size_t)c * XCH + (size_t)(bi * 9 + ki) * WPITCH + (bj * 9 + kj)];
    }
    g_Bmat[idx] = __float2bfloat16(v);
}

// ---------------- main fused kernel ----------------
__global__ void __launch_bounds__(256, 2) cross_head_main(
    const float* __restrict__ attn,
    const float* __restrict__ x,
    float* __restrict__ out)
{
    extern __shared__ char smem[];
    const uint32_t sbase = smem_to_u32(smem);
    const int tid  = threadIdx.x;
    const int wid  = tid >> 5;
    const int lane = tid & 31;
    const int c    = blockIdx.x / NBLK_M;
    const int mb   = blockIdx.x % NBLK_M;

    // warp tile: 2 m-groups x 4 n-groups; each warp does m32 x n24
    const int mbase = (wid >> 2) * 32;
    const int nbase = (wid & 3) * 24;

    // ---- producer addressing: thread owns 32B (8 floats) x 2 rows per chunk ----
    const int r0  = tid >> 3;                  // 0..31; rows r0, r0+32
    const int seg = tid & 7;                   // 32B segment within 64-col chunk
    const float* gA[2];
    #pragma unroll
    for (int g = 0; g < 2; g++)
        gA[g] = attn + ((size_t)c * LL + (size_t)(mb * TM + r0 + 32 * g)) * LL + seg * 8;
    const __nv_bfloat16* gB = g_Bmat + (size_t)c * BNROWS * LL;

    // A STS offsets within a stage (pitch-144, conflict-free)
    uint32_t aSts[2];
    #pragma unroll
    for (int g = 0; g < 2; g++)
        aSts[g] = (uint32_t)((r0 + 32 * g) * PITCH + seg * 16);

    // B cp.async indices: 3 x 16B per thread per chunk (96 rows x 8 segs = 768)
    int brow_[3];
    uint32_t bSts[3];
    #pragma unroll
    for (int j = 0; j < 3; j++) {
        int idx = tid + j * 256;               // 0..767
        brow_[j] = idx >> 3;
        bSts[j]  = (uint32_t)(brow_[j] * PITCH + (idx & 7) * 16);
    }

    // ---- ldmatrix lane addressing (pitch-144, no xor) ----
    const int la_row = (lane & 7) + ((lane >> 3) & 1) * 8;
    const int la_col = (lane >> 4) * 16;                       // byte
    uint32_t aBase[2];
    #pragma unroll
    for (int mi = 0; mi < 2; mi++)
        aBase[mi] = (uint32_t)((mbase + 16 * mi + la_row) * PITCH) + (uint32_t)la_col;
    const int lb_n   = (lane & 7) + (lane >> 4) * 8;
    const int lb_col = ((lane >> 3) & 1) * 16;                 // byte
    const uint32_t bBase4 = (uint32_t)((nbase + lb_n) * PITCH) + (uint32_t)lb_col;
    const uint32_t bBase2 = (uint32_t)((nbase + 16 + (lane & 7)) * PITCH)
                          + (uint32_t)(((lane >> 3) & 1) * 16);

    float acc[2][3][4];
    #pragma unroll
    for (int mi = 0; mi < 2; mi++)
        #pragma unroll
        for (int nj = 0; nj < 3; nj++)
            #pragma unroll
            for (int r = 0; r < 4; r++) acc[mi][nj][r] = 0.0f;

    int cnt[2] = {0, 0};

    // STS + nz-count helper pattern is repeated; keep as lambda (inlined)
    auto sts_count = [&](float4 (&rs)[4], uint32_t saStage) {
        #pragma unroll
        for (int g = 0; g < 2; g++) {
            float4 v0 = rs[2 * g], v1 = rs[2 * g + 1];
            cnt[g] += (v0.x != 0.0f) + (v0.y != 0.0f) + (v0.z != 0.0f) + (v0.w != 0.0f)
                    + (v1.x != 0.0f) + (v1.y != 0.0f) + (v1.z != 0.0f) + (v1.w != 0.0f);
            uint4 p;
            asm("cvt.rn.bf16x2.f32 %0, %1, %2;" : "=r"(p.x) : "f"(v0.y), "f"(v0.x));
            asm("cvt.rn.bf16x2.f32 %0, %1, %2;" : "=r"(p.y) : "f"(v0.w), "f"(v0.z));
            asm("cvt.rn.bf16x2.f32 %0, %1, %2;" : "=r"(p.z) : "f"(v1.y), "f"(v1.x));
            asm("cvt.rn.bf16x2.f32 %0, %1, %2;" : "=r"(p.w) : "f"(v1.w), "f"(v1.z));
            asm volatile("st.shared.v4.b32 [%0], {%1,%2,%3,%4};"
                         :: "r"(saStage + aSts[g]), "r"(p.x), "r"(p.y), "r"(p.z), "r"(p.w));
        }
    };
    auto ldg_a = [&](int chunk, float4 (&rl)[4]) {
        #pragma unroll
        for (int g = 0; g < 2; g++) {
            const float4* pa = reinterpret_cast<const float4*>(gA[g] + chunk * KC);
            rl[2 * g]     = __ldcs(pa);
            rl[2 * g + 1] = __ldcs(pa + 1);
        }
    };
    auto cp_b = [&](int chunk, int stage) {
        const uint32_t dst = sbase + (uint32_t)SM_B(stage);
        #pragma unroll
        for (int j = 0; j < 3; j++)
            CP_ASYNC_CG(dst + bSts[j], gB + (size_t)brow_[j] * LL + chunk * KC + seg * 8);
    };

    float4 ra0[4], ra1[4];

    // ---- prologue: B(0) async; A(0) -> regs -> smem stage0 (counted); A(1) -> regs ----
    cp_b(0, 0);
    CP_COMMIT();                               // group: {B0}
    ldg_a(0, ra0);
    sts_count(ra0, sbase + (uint32_t)SM_A(0));
    ldg_a(1, ra0);                             // ra0 now holds A(1)

    // ---- main loop: one __syncthreads per chunk, 3-stage rotation ----
    // step(i): STS A(i+1) from rs; cp.async B(i+1); LDG A(i+2) -> rl; wait; bar; compute(i)
    auto step = [&](int i, int cs, float4 (&rs)[4], float4 (&rl)[4]) {
        const int ns = (cs == 2) ? 0 : cs + 1;          // stage for chunk i+1
        if (i + 1 < NCHUNKS) {
            sts_count(rs, sbase + (uint32_t)SM_A(ns));
            cp_b(i + 1, ns);
        }
        CP_COMMIT();                                    // possibly empty group
        if (i + 2 < NCHUNKS) ldg_a(i + 2, rl);
        CP_WAIT(1);                                     // B(i) complete
        __syncthreads();                                // A(i), B(i) visible; WAR safe (3 stages)

        const uint32_t saA = sbase + (uint32_t)SM_A(cs);
        const uint32_t saB = sbase + (uint32_t)SM_B(cs);
        #pragma unroll
        for (int ks = 0; ks < 4; ks++) {
            const uint32_t kb = (uint32_t)(ks * 32);
            uint32_t afr[2][4];
            #pragma unroll
            for (int mi = 0; mi < 2; mi++)
                ldmx4(afr[mi], saA + aBase[mi] + kb);
            uint32_t bfr[6];
            ldmx4(bfr,     saB + bBase4 + kb);
            ldmx2(bfr + 4, saB + bBase2 + kb);
            #pragma unroll
            for (int mi = 0; mi < 2; mi++)
                #pragma unroll
                for (int nj = 0; nj < 3; nj++)
                    mma16816(acc[mi][nj], afr[mi], bfr[nj * 2], bfr[nj * 2 + 1]);
        }
    };

    int cs = 0;                                         // compute stage of chunk i
    for (int i = 0; i < NCHUNKS; i += 2) {
        step(i,     cs, ra0, ra1);
        cs = (cs == 2) ? 0 : cs + 1;
        step(i + 1, cs, ra1, ra0);
        cs = (cs == 2) ? 0 : cs + 1;
    }

    // ---- nz: reduce 8 lanes (same row group) per row ----
    __syncthreads();   // reuse of smem nz region is safe (never written in loop)
    #pragma unroll
    for (int g = 0; g < 2; g++) {
        int v = cnt[g];
        v += __shfl_xor_sync(0xFFFFFFFFu, v, 1);
        v += __shfl_xor_sync(0xFFFFFFFFu, v, 2);
        v += __shfl_xor_sync(0xFFFFFFFFu, v, 4);
        if (seg == 0)
            reinterpret_cast<float*>(smem + SM_NZ)[r0 + 32 * g] = (float)v;
    }
    __syncthreads();

    // ---- epilogue: scale by 1/nz, fold, corr*x + x, leaky relu ----
    const float* snz = reinterpret_cast<const float*>(smem + SM_NZ);
    #pragma unroll
    for (int mi = 0; mi < 2; mi++) {
        #pragma unroll
        for (int hr = 0; hr < 2; hr++) {
            const int m = mbase + 16 * mi + (lane >> 2) + 8 * hr;
            const float inv = 1.0f / (snz[m] + 1e-5f);
            const int l  = mb * TM + m;
            const int bi = l / NW, bj = l % NW;
            const size_t base = (size_t)c * XCH + (size_t)(bi * 9) * WPITCH + (size_t)(bj * 9);
            const float* xp = x + base;
            float* op = out + base;
            #pragma unroll
            for (int nj = 0; nj < 3; nj++) {
                #pragma unroll
                for (int e = 0; e < 2; e++) {
                    const int n = nbase + 8 * nj + 2 * (lane & 3) + e;
                    if (n < 81) {
                        const int ki = n / 9, kj = n % 9;
                        const float a  = acc[mi][nj][hr * 2 + e] * inv;
                        const float xv = xp[ki * WPITCH + kj];
                        const float o  = fmaf(a, xv, xv);
                        op[ki * WPITCH + kj] = (o >= 0.0f) ? o : 0.2f * o;
                    }
                }
            }
        }
    }
}

// ---------------- launch ----------------
extern "C" void kernel_launch(void* const* d_in, const int* in_sizes, int n_in,
                              void* d_out, int out_size) {
    const float* x;
    const float* attn;
    if (in_sizes[0] == 1492992) {           // x is 1*4*72*72*72
        x = (const float*)d_in[0];
        attn = (const float*)d_in[1];
    } else {
        x = (const float*)d_in[1];
        attn = (const float*)d_in[0];
    }
    cudaFuncSetAttribute(cross_head_main,
                         cudaFuncAttributeMaxDynamicSharedMemorySize, SMEM_BYTES);
    build_b_kernel<<<6912, 256>>>(x);       // 6912*256 == 4*96*4608
    cross_head_main<<<NCH * NBLK_M, 256, SMEM_BYTES>>>(attn, x, (float*)d_out);
}